// round 4
// baseline (speedup 1.0000x reference)
#include <cuda_runtime.h>
#include <cstdint>

#define T_SEQ    512
#define BATCH    4096
#define IND      64
#define HID      128
#define MT       32            // batch rows per CTA
#define NCTA     (BATCH / MT)  // 128
#define KTOT     192           // 64 (ih) + 128 (hh)
#define NKT      (KTOT / 8)    // 24 k-tiles of 8
#define NTHREADS 512           // 16 warps: 2 row-tiles x 8 col-groups
#define SLAB     132           // floats per [rt][kt] slab: 32 lanes * 4 + 4 pad

// ---------------------------------------------------------------------------

__device__ __forceinline__ uint32_t f2tf32(float f) {
    uint32_t u;
    asm("cvt.rna.tf32.f32 %0, %1;" : "=r"(u) : "f"(f));
    return u;
}

// D += A(16x8) * B(8x8)^T, tf32 inputs, fp32 accum
__device__ __forceinline__ void mma8(float* d, const uint32_t* a, uint32_t b0, uint32_t b1) {
    asm volatile(
        "mma.sync.aligned.m16n8k8.row.col.f32.tf32.tf32.f32 "
        "{%0,%1,%2,%3}, {%4,%5,%6,%7}, {%8,%9}, {%0,%1,%2,%3};"
        : "+f"(d[0]), "+f"(d[1]), "+f"(d[2]), "+f"(d[3])
        : "r"(a[0]), "r"(a[1]), "r"(a[2]), "r"(a[3]), "r"(b0), "r"(b1));
}

// accurate tanh: ex2.approx + rcp.approx, abs err ~1e-6, saturates at +-1
__device__ __forceinline__ float tanh_acc(float v) {
    float e = __expf(2.0f * v);
    return 1.0f - __fdividef(2.0f, e + 1.0f);
}

// float index of A element (r in 0..31, k in 0..191) inside the fragment array.
// Fragment a0..a3 of mma lane l covers rows {g, g+8} x cols {k, k+4}:
//   lane' = (r&7)*4 + (k&3),  j = ((k>>2)&1)*2 + ((r>>3)&1)
__device__ __forceinline__ int frag_fidx(int r, int k) {
    int slab  = ((r >> 4) * NKT + (k >> 3));
    int lanep = ((r & 7) << 2) | (k & 3);
    int j     = (((k >> 2) & 1) << 1) | ((r >> 3) & 1);
    return slab * SLAB + (lanep << 2) + j;
}

// ---------------------------------------------------------------------------

__global__ void __launch_bounds__(NTHREADS, 1)
rnn_kernel(const float* __restrict__ x, const float* __restrict__ Wih,
           const float* __restrict__ bih, const float* __restrict__ Whh,
           const float* __restrict__ bhh, float* __restrict__ out) {
    __shared__ float afrag[2 * NKT * SLAB];   // 6336 floats = 25.3 KB
    __shared__ float bsum[HID];

    const int tid = threadIdx.x;
    const int wid = tid >> 5;
    const int lid = tid & 31;
    const int rt  = wid >> 3;        // row tile: rows rt*16 .. +15
    const int cg  = wid & 7;         // col group: cols cg*16 .. +15
    const int b0  = blockIdx.x * MT;

    // ---- B fragments (weights) resident in registers, tf32-rounded ----
    // For n-tile nt = 2*cg + i: lane holds W[nt*8 + lid/4, kt*8 + lid%4 (+4)]
    uint32_t breg[2][NKT][2];
#pragma unroll
    for (int i = 0; i < 2; i++) {
        const int n = (((cg << 1) + i) << 3) + (lid >> 2);
#pragma unroll
        for (int kt = 0; kt < 8; kt++)
#pragma unroll
            for (int jb = 0; jb < 2; jb++) {
                int k = (kt << 3) + (lid & 3) + (jb << 2);
                breg[i][kt][jb] = f2tf32(Wih[n * IND + k]);
            }
#pragma unroll
        for (int kt = 8; kt < NKT; kt++)
#pragma unroll
            for (int jb = 0; jb < 2; jb++) {
                int k = (kt << 3) + (lid & 3) + (jb << 2) - IND;
                breg[i][kt][jb] = f2tf32(Whh[n * HID + k]);
            }
    }

    if (tid < HID) bsum[tid] = bih[tid] + bhh[tid];

    // ---- zero A fragments (h_{-1} = 0), then lay in x_0 ----
    for (int i = tid; i < 2 * NKT * SLAB; i += NTHREADS) afrag[i] = 0.0f;
    __syncthreads();

    const int xr  = tid >> 4;          // row 0..31
    const int xk0 = (tid & 15) << 2;   // k 0,4,..,60
    {
        float4 xv = *(const float4*)(x + (size_t)(b0 + xr) * IND + xk0);
        afrag[frag_fidx(xr, xk0 + 0)] = __uint_as_float(f2tf32(xv.x));
        afrag[frag_fidx(xr, xk0 + 1)] = __uint_as_float(f2tf32(xv.y));
        afrag[frag_fidx(xr, xk0 + 2)] = __uint_as_float(f2tf32(xv.z));
        afrag[frag_fidx(xr, xk0 + 3)] = __uint_as_float(f2tf32(xv.w));
    }
    __syncthreads();

    const int   rbase = (rt << 4) + (lid >> 2);       // low row of this lane
    const float* aldb = &afrag[(rt * NKT) * SLAB + (lid << 2)];

    for (int t = 0; t < T_SEQ; t++) {
        // prefetch x_{t+1} (latency hidden under MMA phase)
        float4 xv;
        if (t + 1 < T_SEQ)
            xv = *(const float4*)(x + ((size_t)(t + 1) * BATCH + b0 + xr) * IND + xk0);

        // ---- MMA phase: D = [x_t | h] @ [W_ih | W_hh]^T, K = 192 ----
        float d[2][4] = {{0.f, 0.f, 0.f, 0.f}, {0.f, 0.f, 0.f, 0.f}};
#pragma unroll
        for (int kt = 0; kt < NKT; kt++) {
            uint32_t a[4];
            *(float4*)a = *(const float4*)(aldb + kt * SLAB);   // LDS.128, conflict-free
            mma8(d[0], a, breg[0][kt][0], breg[0][kt][1]);
            mma8(d[1], a, breg[1][kt][0], breg[1][kt][1]);
        }

        // ---- epilogue: bias + tanh ----
        float v[2][4];
#pragma unroll
        for (int i = 0; i < 2; i++) {
            const int c0 = (((cg << 1) + i) << 3) + ((lid & 3) << 1);  // even
            const float2 bb = *(const float2*)&bsum[c0];
            v[i][0] = tanh_acc(d[i][0] + bb.x);   // (rbase,   c0)
            v[i][1] = tanh_acc(d[i][1] + bb.y);   // (rbase,   c0+1)
            v[i][2] = tanh_acc(d[i][2] + bb.x);   // (rbase+8, c0)
            v[i][3] = tanh_acc(d[i][3] + bb.y);   // (rbase+8, c0+1)
        }

        __syncthreads();   // all warps done reading afrag

        if (t + 1 < T_SEQ) {
            // write h_t fragments: pairs (v_lo, v_hi) are j-adjacent -> STS.64
#pragma unroll
            for (int i = 0; i < 2; i++) {
                const int c0 = (((cg << 1) + i) << 3) + ((lid & 3) << 1);
                const int k0 = IND + c0;                       // k0&3 in {0,2}
                const int base = (rt * NKT + (k0 >> 3)) * SLAB
                               + ((((lid >> 2) << 2) | (k0 & 3)) << 2)
                               + (((k0 >> 2) & 1) << 1);
                float2 p0, p1;
                p0.x = __uint_as_float(f2tf32(v[i][0]));
                p0.y = __uint_as_float(f2tf32(v[i][2]));
                p1.x = __uint_as_float(f2tf32(v[i][1]));
                p1.y = __uint_as_float(f2tf32(v[i][3]));
                *(float2*)&afrag[base]     = p0;   // (rbase, k0), (rbase+8, k0)
                *(float2*)&afrag[base + 4] = p1;   // (rbase, k0+1), (rbase+8, k0+1)
            }
            // write x_{t+1} fragments
            afrag[frag_fidx(xr, xk0 + 0)] = __uint_as_float(f2tf32(xv.x));
            afrag[frag_fidx(xr, xk0 + 1)] = __uint_as_float(f2tf32(xv.y));
            afrag[frag_fidx(xr, xk0 + 2)] = __uint_as_float(f2tf32(xv.z));
            afrag[frag_fidx(xr, xk0 + 3)] = __uint_as_float(f2tf32(xv.w));
            __syncthreads();   // writes visible before next step's reads
        } else {
            // final step: write h_T (unrounded) to gmem
#pragma unroll
            for (int i = 0; i < 2; i++) {
                const int c0 = (((cg << 1) + i) << 3) + ((lid & 3) << 1);
                float* o_lo = out + (size_t)(b0 + rbase) * HID + c0;
                float* o_hi = out + (size_t)(b0 + rbase + 8) * HID + c0;
                o_lo[0] = v[i][0];
                o_lo[1] = v[i][1];
                o_hi[0] = v[i][2];
                o_hi[1] = v[i][3];
            }
        }
    }
}

// ---------------------------------------------------------------------------

extern "C" void kernel_launch(void* const* d_in, const int* in_sizes, int n_in,
                              void* d_out, int out_size) {
    const float* x   = (const float*)d_in[0];
    const float* Wih = (const float*)d_in[1];
    const float* bih = (const float*)d_in[2];
    const float* Whh = (const float*)d_in[3];
    const float* bhh = (const float*)d_in[4];
    float* out = (float*)d_out;

    rnn_kernel<<<NCTA, NTHREADS>>>(x, Wih, bih, Whh, bhh, out);
}

// round 5
// speedup vs baseline: 1.6117x; 1.6117x over previous
#include <cuda_runtime.h>
#include <cuda_fp16.h>
#include <cstdint>

#define T_SEQ    512
#define BATCH    4096
#define IND      64
#define HID      128
#define MT       32            // batch rows per CTA
#define NCTA     (BATCH / MT)  // 128
#define NKT      12            // k-tiles of 16 (K = 192)
#define NTHREADS 256           // 8 warps: 2 row-tiles x 4 col-groups (n=32/warp)
#define BUFU32   (2 * NKT * 128)   // u32 per A buffer (2 rt x 12 kt x 32 lanes x 4 regs)

// ---------------------------------------------------------------------------

__device__ __forceinline__ uint32_t packh2(float a, float b) {
    __half2 h = __floats2half2_rn(a, b);
    return *reinterpret_cast<uint32_t*>(&h);
}

// D += A(16x16) * B(16x8)^T-ish (row.col), fp16 in, fp32 accum
__device__ __forceinline__ void mma16(float* d, const uint32_t* a, uint32_t b0, uint32_t b1) {
    asm volatile(
        "mma.sync.aligned.m16n8k16.row.col.f32.f16.f16.f32 "
        "{%0,%1,%2,%3}, {%4,%5,%6,%7}, {%8,%9}, {%0,%1,%2,%3};"
        : "+f"(d[0]), "+f"(d[1]), "+f"(d[2]), "+f"(d[3])
        : "r"(a[0]), "r"(a[1]), "r"(a[2]), "r"(a[3]), "r"(b0), "r"(b1));
}

// accurate tanh: ex2.approx + rcp.approx, abs err ~1e-6, saturates at +-1
__device__ __forceinline__ float tanh_acc(float v) {
    float e = __expf(2.0f * v);
    return 1.0f - __fdividef(2.0f, e + 1.0f);
}

// u32 index of the half-PAIR (k, k+1) for element row (0..31), k even (0..191)
// inside one A buffer laid out as [rt][kt][lane][4 regs].
// m16n8k16 A frag: lane=(row&7)*4 + ((k&15)>>1)&3 ; reg=((k&15)>>3)*2 + ((row>>3)&1)
__device__ __forceinline__ int xidx(int row, int k) {
    int kt = k >> 4, kk = k & 15;
    int lane = ((row & 7) << 2) | ((kk >> 1) & 3);
    int reg  = ((kk >> 3) << 1) | ((row >> 3) & 1);
    return ((row >> 4) * NKT + kt) * 128 + (lane << 2) + reg;
}

// ---------------------------------------------------------------------------

__global__ void __launch_bounds__(NTHREADS, 1)
rnn_kernel(const float* __restrict__ x, const float* __restrict__ Wih,
           const float* __restrict__ bih, const float* __restrict__ Whh,
           const float* __restrict__ bhh, float* __restrict__ out) {
    __shared__ uint32_t afrag[2][BUFU32];   // ping-pong A = [x_t | h_t] fp16 fragments
    __shared__ float bsum[HID];

    const int tid = threadIdx.x;
    const int wid = tid >> 5;
    const int lid = tid & 31;
    const int rt  = wid >> 2;        // row tile: rows rt*16 .. +15
    const int cg  = wid & 3;         // col group: cols cg*32 .. +31 (4 n-tiles of 8)
    const int b0  = blockIdx.x * MT;

    // ---- B fragments (weights, fp16) resident in registers ----
    // n-tile nt = cg*4 + i: lane holds W[nt*8 + lid/4] at k = kt*16 + 2*(lid%4) + jb*8 (+1)
    uint32_t breg[4][NKT][2];
#pragma unroll
    for (int i = 0; i < 4; i++) {
        const int n = ((cg << 2) + i) * 8 + (lid >> 2);
        const float* wih_r = Wih + n * IND;
        const float* whh_r = Whh + n * HID;
#pragma unroll
        for (int kt = 0; kt < 4; kt++)      // k < 64: W_ih
#pragma unroll
            for (int jb = 0; jb < 2; jb++) {
                int k = (kt << 4) + ((lid & 3) << 1) + (jb << 3);
                breg[i][kt][jb] = packh2(wih_r[k], wih_r[k + 1]);
            }
#pragma unroll
        for (int kt = 4; kt < NKT; kt++)    // k >= 64: W_hh
#pragma unroll
            for (int jb = 0; jb < 2; jb++) {
                int k = (kt << 4) + ((lid & 3) << 1) + (jb << 3) - IND;
                breg[i][kt][jb] = packh2(whh_r[k], whh_r[k + 1]);
            }
    }

    if (tid < HID) bsum[tid] = bih[tid] + bhh[tid];

    // ---- init buffer 0: zeros (h_{-1}=0) + x_0 ----
    for (int i = tid; i < BUFU32; i += NTHREADS) afrag[0][i] = 0u;
    __syncthreads();

    // per-thread x handling: 2 float4 loads/step, scattered as 4 half2 stores
    int   xrow[2], xk0[2], xw0[2], xw1[2];
    const float* xptr[2];
#pragma unroll
    for (int j = 0; j < 2; j++) {
        int idx = tid * 2 + j;
        xrow[j] = idx >> 4;
        xk0[j]  = (idx & 15) << 2;
        xw0[j]  = xidx(xrow[j], xk0[j]);
        xw1[j]  = xidx(xrow[j], xk0[j] + 2);
        xptr[j] = x + (size_t)(b0 + xrow[j]) * IND + xk0[j];
    }
#pragma unroll
    for (int j = 0; j < 2; j++) {
        float4 xv = *(const float4*)xptr[j];
        afrag[0][xw0[j]] = packh2(xv.x, xv.y);
        afrag[0][xw1[j]] = packh2(xv.z, xv.w);
    }
    __syncthreads();

    const int rbase = (rt << 4) + (lid >> 2);   // low row of this lane

    for (int t = 0; t < T_SEQ; t++) {
        // prefetch x_{t+1} (hidden under MMA phase)
        float4 xv0, xv1;
        if (t + 1 < T_SEQ) {
            const size_t off = (size_t)(t + 1) * BATCH * IND;
            xv0 = *(const float4*)(xptr[0] + off);
            xv1 = *(const float4*)(xptr[1] + off);
        }

        // ---- MMA: D = [x_t | h] @ [W_ih | W_hh]^T, K = 192 (12 fp16 k-tiles) ----
        const uint32_t* ar = afrag[t & 1] + rt * NKT * 128;
        float d[4][4] = {{0.f,0.f,0.f,0.f},{0.f,0.f,0.f,0.f},
                         {0.f,0.f,0.f,0.f},{0.f,0.f,0.f,0.f}};
#pragma unroll
        for (int kt = 0; kt < NKT; kt++) {
            uint4 av = *(const uint4*)(ar + kt * 128 + (lid << 2));  // LDS.128, conflict-free
            mma16(d[0], (const uint32_t*)&av, breg[0][kt][0], breg[0][kt][1]);
            mma16(d[1], (const uint32_t*)&av, breg[1][kt][0], breg[1][kt][1]);
            mma16(d[2], (const uint32_t*)&av, breg[2][kt][0], breg[2][kt][1]);
            mma16(d[3], (const uint32_t*)&av, breg[3][kt][0], breg[3][kt][1]);
        }

        // ---- epilogue: bias + tanh ----
        float v[4][4];
#pragma unroll
        for (int i = 0; i < 4; i++) {
            const int c0 = (((cg << 2) + i) << 3) + ((lid & 3) << 1);
            const float2 bb = *(const float2*)&bsum[c0];
            v[i][0] = tanh_acc(d[i][0] + bb.x);   // (rbase,   c0)
            v[i][1] = tanh_acc(d[i][1] + bb.y);   // (rbase,   c0+1)
            v[i][2] = tanh_acc(d[i][2] + bb.x);   // (rbase+8, c0)
            v[i][3] = tanh_acc(d[i][3] + bb.y);   // (rbase+8, c0+1)
        }

        if (t + 1 < T_SEQ) {
            // write h_t + x_{t+1} into the OTHER buffer; one barrier per step
            uint32_t* aw = afrag[(t + 1) & 1];
            // h: n-tiles 2j,2j+1 fill all 4 regs of slab kt=4+cg*2+j -> STS.128
#pragma unroll
            for (int j = 0; j < 2; j++) {
                const int kt = 4 + (cg << 1) + j;
                uint4 pk;
                pk.x = packh2(v[2*j][0],   v[2*j][1]);
                pk.y = packh2(v[2*j][2],   v[2*j][3]);
                pk.z = packh2(v[2*j+1][0], v[2*j+1][1]);
                pk.w = packh2(v[2*j+1][2], v[2*j+1][3]);
                *(uint4*)(aw + (rt * NKT + kt) * 128 + (lid << 2)) = pk;
            }
            aw[xw0[0]] = packh2(xv0.x, xv0.y);
            aw[xw1[0]] = packh2(xv0.z, xv0.w);
            aw[xw0[1]] = packh2(xv1.x, xv1.y);
            aw[xw1[1]] = packh2(xv1.z, xv1.w);
            __syncthreads();
        } else {
            // final step: h_T (full fp32) to gmem
#pragma unroll
            for (int i = 0; i < 4; i++) {
                const int c0 = (((cg << 2) + i) << 3) + ((lid & 3) << 1);
                float2 lo = make_float2(v[i][0], v[i][1]);
                float2 hi = make_float2(v[i][2], v[i][3]);
                *(float2*)(out + (size_t)(b0 + rbase) * HID + c0)     = lo;
                *(float2*)(out + (size_t)(b0 + rbase + 8) * HID + c0) = hi;
            }
        }
    }
}

// ---------------------------------------------------------------------------

extern "C" void kernel_launch(void* const* d_in, const int* in_sizes, int n_in,
                              void* d_out, int out_size) {
    const float* x   = (const float*)d_in[0];
    const float* Wih = (const float*)d_in[1];
    const float* bih = (const float*)d_in[2];
    const float* Whh = (const float*)d_in[3];
    const float* bhh = (const float*)d_in[4];
    float* out = (float*)d_out;

    rnn_kernel<<<NCTA, NTHREADS>>>(x, Wih, bih, Whh, bhh, out);
}